// round 1
// baseline (speedup 1.0000x reference)
#include <cuda_runtime.h>

#define D       64
#define K       512
#define KPAD    516     // pad so epilogue gather Es[d*KPAD + kmin] is only 4-way conflicted
#define ROWS    256     // rows per block
#define THREADS 256

__device__ double g_loss_sum;

__global__ void vq_zero_loss_kernel() {
    g_loss_sum = 0.0;
}

__global__ __launch_bounds__(THREADS, 1)
void vq_main_kernel(const float* __restrict__ x,
                    const float* __restrict__ E,
                    float* __restrict__ out) {
    extern __shared__ float smem[];
    float* Es     = smem;                 // [D][KPAD]
    float* enorm  = Es + D * KPAD;        // [K]
    int*   kmin_s = (int*)(enorm + K);    // [ROWS]
    __shared__ float red[THREADS / 32];

    const int tid = threadIdx.x;
    const int rowBase = blockIdx.x * ROWS;

    // ---- stage E into smem (padded layout) ----
    for (int i = tid; i < (D * K) / 4; i += THREADS) {
        int d = (i * 4) / K;
        int k = (i * 4) % K;
        float4 v = ((const float4*)E)[i];
        *(float4*)&Es[d * KPAD + k] = v;
    }
    __syncthreads();

    // ---- code norms ||e_k||^2 (redundant per block, trivial cost) ----
    for (int k = tid; k < K; k += THREADS) {
        float s = 0.f;
        #pragma unroll
        for (int d = 0; d < D; d++) {
            float e = Es[d * KPAD + k];
            s = fmaf(e, e, s);
        }
        enorm[k] = s;
    }

    // ---- load this thread's row into registers ----
    float xr[D];
    {
        const float4* xp = (const float4*)(x + (size_t)(rowBase + tid) * D);
        #pragma unroll
        for (int i = 0; i < D / 4; i++) {
            float4 v = xp[i];
            xr[4*i+0] = v.x; xr[4*i+1] = v.y; xr[4*i+2] = v.z; xr[4*i+3] = v.w;
        }
    }
    __syncthreads();

    // ---- score all K codes: s_k = ||e_k||^2 - 2 x.e_k ; running argmin ----
    float best  = 3.402823466e38f;
    int   bestk = 0;
    #pragma unroll 1
    for (int k0 = 0; k0 < K; k0 += 8) {
        float acc0 = 0.f, acc1 = 0.f, acc2 = 0.f, acc3 = 0.f;
        float acc4 = 0.f, acc5 = 0.f, acc6 = 0.f, acc7 = 0.f;
        const float* ebase = &Es[k0];
        #pragma unroll
        for (int d = 0; d < D; d++) {
            const float4* ep = (const float4*)(ebase + d * KPAD);
            float4 e0 = ep[0];
            float4 e1 = ep[1];
            float xd = xr[d];
            acc0 = fmaf(xd, e0.x, acc0);
            acc1 = fmaf(xd, e0.y, acc1);
            acc2 = fmaf(xd, e0.z, acc2);
            acc3 = fmaf(xd, e0.w, acc3);
            acc4 = fmaf(xd, e1.x, acc4);
            acc5 = fmaf(xd, e1.y, acc5);
            acc6 = fmaf(xd, e1.z, acc6);
            acc7 = fmaf(xd, e1.w, acc7);
        }
        float s;
        s = fmaf(-2.f, acc0, enorm[k0+0]); if (s < best) { best = s; bestk = k0+0; }
        s = fmaf(-2.f, acc1, enorm[k0+1]); if (s < best) { best = s; bestk = k0+1; }
        s = fmaf(-2.f, acc2, enorm[k0+2]); if (s < best) { best = s; bestk = k0+2; }
        s = fmaf(-2.f, acc3, enorm[k0+3]); if (s < best) { best = s; bestk = k0+3; }
        s = fmaf(-2.f, acc4, enorm[k0+4]); if (s < best) { best = s; bestk = k0+4; }
        s = fmaf(-2.f, acc5, enorm[k0+5]); if (s < best) { best = s; bestk = k0+5; }
        s = fmaf(-2.f, acc6, enorm[k0+6]); if (s < best) { best = s; bestk = k0+6; }
        s = fmaf(-2.f, acc7, enorm[k0+7]); if (s < best) { best = s; bestk = k0+7; }
    }
    kmin_s[tid] = bestk;
    __syncthreads();

    // ---- epilogue: coalesced straight-through output + loss partial ----
    float lsum = 0.f;
    const float* xg = x   + (size_t)rowBase * D;
    float*       og = out + (size_t)rowBase * D;
    #pragma unroll 4
    for (int j = 0; j < (ROWS * D) / THREADS; j++) {   // 64 iters
        int idx = j * THREADS + tid;                   // coalesced
        int r = idx >> 6;
        int d = idx & 63;
        float q  = Es[d * KPAD + kmin_s[r]];
        float xv = xg[idx];
        // mimic reference arithmetic exactly: out = x + (q - x)
        float t = q - xv;
        og[idx] = xv + t;
        lsum = fmaf(t, t, lsum);
    }

    // ---- block reduction of loss partial ----
    #pragma unroll
    for (int off = 16; off > 0; off >>= 1)
        lsum += __shfl_xor_sync(0xffffffffu, lsum, off);
    if ((tid & 31) == 0) red[tid >> 5] = lsum;
    __syncthreads();
    if (tid == 0) {
        float s = 0.f;
        #pragma unroll
        for (int w = 0; w < THREADS / 32; w++) s += red[w];
        atomicAdd(&g_loss_sum, (double)s);
    }
}

__global__ void vq_finalize_kernel(float* __restrict__ out, int N) {
    // loss = commitment + codebook = 2 * mean((q - x)^2)
    out[(size_t)N * D] = (float)(2.0 * g_loss_sum / ((double)N * (double)D));
}

extern "C" void kernel_launch(void* const* d_in, const int* in_sizes, int n_in,
                              void* d_out, int out_size) {
    const float* x = (const float*)d_in[0];
    const float* E = (const float*)d_in[1];
    float* out = (float*)d_out;

    const int N = in_sizes[0] / D;   // 65536 rows

    const size_t smem = (size_t)(D * KPAD + K) * sizeof(float) + ROWS * sizeof(int);
    cudaFuncSetAttribute(vq_main_kernel,
                         cudaFuncAttributeMaxDynamicSharedMemorySize, (int)smem);

    vq_zero_loss_kernel<<<1, 1>>>();
    vq_main_kernel<<<N / ROWS, THREADS, smem>>>(x, E, out);
    if (out_size > N * D) {
        vq_finalize_kernel<<<1, 1>>>(out, N);
    }
}

// round 3
// speedup vs baseline: 3.0973x; 3.0973x over previous
#include <cuda_runtime.h>
#include <cuda_fp16.h>
#include <cstdint>

#define D        64
#define KC       512
#define BROWS    256
#define THREADS  256
#define DELTA    8.0e-3f
#define C_OFS    16.0f

// ---------------- device globals (scratch; allocs forbidden) ----------------
__device__ __align__(16) __half g_e16[KC * D];     // fp16 codebook [k][d]
__device__ __align__(16) float  g_eT[KC * D];      // fp32 codebook [k][d] (transposed)
__device__ float  g_enormC2[KC];                   // -(||e_k||^2 + C)/2
__device__ double g_loss_sum;
__device__ int    g_counter = 0;

// ---------------- smem layout (dynamic) ----------------
#define S_E      0                      // 512 * 128B (fp16, swizzled)      = 65536
#define S_X      65536                  // 256 * 128B (fp16, swizzled)      = 32768
#define S_EN     98304                  // 512 * 4B                         = 2048
#define S_KMIN   100352                 // 256 * 4B                         = 1024
#define S_TOTAL  101376

__device__ __forceinline__ uint32_t smem_u32(const void* p) {
    uint32_t a;
    asm("{ .reg .u64 t; cvta.to.shared.u64 t, %1; cvt.u32.u64 %0, t; }" : "=r"(a) : "l"(p));
    return a;
}

__device__ __forceinline__ void ldmatrix_x4(uint32_t* r, uint32_t addr) {
    asm volatile("ldmatrix.sync.aligned.m8n8.x4.shared.b16 {%0,%1,%2,%3}, [%4];"
                 : "=r"(r[0]), "=r"(r[1]), "=r"(r[2]), "=r"(r[3]) : "r"(addr));
}

__device__ __forceinline__ void mma16816(float& c0, float& c1, float& c2, float& c3,
                                         const uint32_t* a, uint32_t b0, uint32_t b1) {
    asm volatile("mma.sync.aligned.m16n8k16.row.col.f32.f16.f16.f32 "
                 "{%0,%1,%2,%3}, {%4,%5,%6,%7}, {%8,%9}, {%0,%1,%2,%3};"
                 : "+f"(c0), "+f"(c1), "+f"(c2), "+f"(c3)
                 : "r"(a[0]), "r"(a[1]), "r"(a[2]), "r"(a[3]), "r"(b0), "r"(b1));
}

// ================= prep: fp16 codebook, fp32 transposed codebook, norms =================
__global__ void vq_prep_kernel(const float* __restrict__ E) {
    __shared__ float sq[D];
    int k = blockIdx.x, d = threadIdx.x;
    float e = E[d * KC + k];
    g_e16[k * D + d] = __float2half_rn(e);
    g_eT[k * D + d]  = e;
    sq[d] = e * e;
    __syncthreads();
    if (d == 0) {
        float s = 0.f;
        #pragma unroll
        for (int i = 0; i < D; i++) s += sq[i];
        g_enormC2[k] = -0.5f * (s + C_OFS);
        if (k == 0) g_loss_sum = 0.0;
    }
}

// ================= main =================
__global__ __launch_bounds__(THREADS, 1)
void vq_main_kernel(const float* __restrict__ x,
                    float* __restrict__ out,
                    int writeLoss, int Nrows) {
    extern __shared__ __align__(16) char sm[];
    const uint32_t sb = smem_u32(sm);
    __shared__ float red[8];

    const int tid  = threadIdx.x;
    const int w    = tid >> 5, lane = tid & 31;
    const int m4   = lane & 3,  q8  = lane >> 2;
    const int rowBase = blockIdx.x * BROWS;

    // ---- stage E fp16 (swizzled rows of 128B) ----
    {
        const uint4* ge = (const uint4*)g_e16;
        #pragma unroll
        for (int i = 0; i < 16; i++) {
            int f = i * THREADS + tid;            // 16B chunk id
            int c = f >> 3, seg = f & 7;
            *(uint4*)(sm + S_E + c * 128 + ((seg * 16) ^ ((c & 7) << 4))) = ge[f];
        }
        float* en = (float*)(sm + S_EN);
        en[tid] = g_enormC2[tid];
        en[THREADS + tid] = g_enormC2[THREADS + tid];
    }
    // ---- stage X fp16 (swizzled rows of 128B) ----
    {
        const float4* xg = (const float4*)(x + (size_t)rowBase * D);
        #pragma unroll
        for (int i = 0; i < 16; i++) {
            int f = i * THREADS + tid;            // float4 id
            float4 v = xg[f];
            int row = f >> 4, seg = f & 15;
            uint32_t h0 = __half_as_ushort(__float2half_rn(v.x));
            uint32_t h1 = __half_as_ushort(__float2half_rn(v.y));
            uint32_t h2 = __half_as_ushort(__float2half_rn(v.z));
            uint32_t h3 = __half_as_ushort(__float2half_rn(v.w));
            uint2 u = make_uint2(h0 | (h1 << 16), h2 | (h3 << 16));
            *(uint2*)(sm + S_X + row * 128 + ((seg * 8) ^ ((row & 7) << 4))) = u;
        }
    }
    __syncthreads();

    // ---- preload A fragments: 2 m16 tiles x 4 k-steps ----
    uint32_t afr[2][4][4];
    const int tb0 = w * 32;
    #pragma unroll
    for (int t2 = 0; t2 < 2; t2++) {
        #pragma unroll
        for (int s = 0; s < 4; s++) {
            int row = tb0 + t2 * 16 + (lane & 15);
            uint32_t off = (uint32_t)(s * 32 + (lane >> 4) * 16) ^ (uint32_t)((row & 7) << 4);
            ldmatrix_x4(afr[t2][s], sb + S_X + row * 128 + off);
        }
    }

    // ---- sweep 512 codes; packed-key top-2 per tracked row ----
    uint32_t k1[4], k2[4];
    #pragma unroll
    for (int i = 0; i < 4; i++) { k1[i] = 0x7F800000u; k2[i] = 0x7F800000u; }

    #pragma unroll 2
    for (int n0 = 0; n0 < KC; n0 += 8) {
        const int c = n0 + q8;
        const char* erow = sm + S_E + c * 128;
        const uint32_t swz = (uint32_t)((c & 7) << 4);
        uint32_t b[4][2];
        #pragma unroll
        for (int s = 0; s < 4; s++) {
            uint32_t doff = (uint32_t)(s * 32 + m4 * 4);
            b[s][0] = *(const uint32_t*)(erow + (doff ^ swz));
            b[s][1] = *(const uint32_t*)(erow + ((doff + 16) ^ swz));
        }
        float2 en2 = *(const float2*)(sm + S_EN + (n0 + 2 * m4) * 4);
        const uint32_t col0 = (uint32_t)(n0 + 2 * m4), col1 = col0 + 1;

        #pragma unroll
        for (int t2 = 0; t2 < 2; t2++) {
            float a0 = en2.x, a1 = en2.y, a2 = en2.x, a3 = en2.y;
            #pragma unroll
            for (int s = 0; s < 4; s++) mma16816(a0, a1, a2, a3, afr[t2][s], b[s][0], b[s][1]);

            // rowA = tb0 + t2*16 + q8 (a0,a1) ; rowB = rowA+8 (a2,a3)
            uint32_t key, mx;
            int iA = t2 * 2, iB = iA + 1;
            key = (__float_as_uint(-2.f * a0) & 0xFFFFFE00u) | col0;
            mx = umax(k1[iA], key); k1[iA] = umin(k1[iA], key); k2[iA] = umin(k2[iA], mx);
            key = (__float_as_uint(-2.f * a1) & 0xFFFFFE00u) | col1;
            mx = umax(k1[iA], key); k1[iA] = umin(k1[iA], key); k2[iA] = umin(k2[iA], mx);
            key = (__float_as_uint(-2.f * a2) & 0xFFFFFE00u) | col0;
            mx = umax(k1[iB], key); k1[iB] = umin(k1[iB], key); k2[iB] = umin(k2[iB], mx);
            key = (__float_as_uint(-2.f * a3) & 0xFFFFFE00u) | col1;
            mx = umax(k1[iB], key); k1[iB] = umin(k1[iB], key); k2[iB] = umin(k2[iB], mx);
        }
    }

    // ---- merge top-2 across the 4 lanes sharing each row ----
    #pragma unroll
    for (int i = 0; i < 4; i++) {
        #pragma unroll
        for (int off = 1; off <= 2; off <<= 1) {
            uint32_t o1 = __shfl_xor_sync(0xffffffffu, k1[i], off);
            uint32_t o2 = __shfl_xor_sync(0xffffffffu, k2[i], off);
            uint32_t mx = umax(k1[i], o1);
            k1[i] = umin(k1[i], o1);
            k2[i] = umin(umin(k2[i], o2), mx);
        }
    }

    // ---- finalize rows: certified refinement on narrow gaps ----
    int* skm = (int*)(sm + S_KMIN);
    if (m4 == 0) {
        const float* en = (const float*)(sm + S_EN);
        #pragma unroll
        for (int i = 0; i < 4; i++) {
            int row = tb0 + (i >> 1) * 16 + q8 + (i & 1) * 8;
            int c1 = (int)(k1[i] & 511u), c2 = (int)(k2[i] & 511u);
            float v1 = __uint_as_float(k1[i] & 0xFFFFFE00u);
            float v2 = __uint_as_float(k2[i] & 0xFFFFFE00u);
            int kmin = c1;
            if (v2 - v1 < DELTA) {
                const float* xr = x + (size_t)(rowBase + row) * D;
                const float* e1 = g_eT + c1 * D;
                const float* e2 = g_eT + c2 * D;
                float p0 = 0.f, p1 = 0.f, p2 = 0.f, p3 = 0.f;
                float r0 = 0.f, r1 = 0.f, r2 = 0.f, r3 = 0.f;
                #pragma unroll
                for (int d = 0; d < D; d += 4) {
                    float x0 = xr[d], x1 = xr[d+1], x2 = xr[d+2], x3 = xr[d+3];
                    p0 = fmaf(x0, e1[d],   p0); p1 = fmaf(x1, e1[d+1], p1);
                    p2 = fmaf(x2, e1[d+2], p2); p3 = fmaf(x3, e1[d+3], p3);
                    r0 = fmaf(x0, e2[d],   r0); r1 = fmaf(x1, e2[d+1], r1);
                    r2 = fmaf(x2, e2[d+2], r2); r3 = fmaf(x3, e2[d+3], r3);
                }
                float s1 = -2.f * (((p0 + p1) + (p2 + p3)) + en[c1]);
                float s2 = -2.f * (((r0 + r1) + (r2 + r3)) + en[c2]);
                if (s2 < s1 || (s2 == s1 && c2 < c1)) kmin = c2;
            }
            skm[row] = kmin;
        }
    }
    __syncthreads();

    // ---- epilogue: coalesced straight-through output + loss (exact fp32 q) ----
    float lsum = 0.f;
    const float* xg = x   + (size_t)rowBase * D;
    float*       og = out + (size_t)rowBase * D;
    #pragma unroll 4
    for (int j = 0; j < (BROWS * D) / THREADS; j++) {
        int idx = j * THREADS + tid;
        int r = idx >> 6, d = idx & 63;
        float q  = g_eT[skm[r] * D + d];
        float xv = xg[idx];
        float t = q - xv;
        og[idx] = xv + t;
        lsum = fmaf(t, t, lsum);
    }
    #pragma unroll
    for (int o = 16; o > 0; o >>= 1) lsum += __shfl_xor_sync(0xffffffffu, lsum, o);
    if (lane == 0) red[w] = lsum;
    __syncthreads();
    if (tid == 0) {
        float s = 0.f;
        #pragma unroll
        for (int i = 0; i < 8; i++) s += red[i];
        atomicAdd(&g_loss_sum, (double)s);
        __threadfence();
        int old = atomicAdd(&g_counter, 1);
        if (old == (int)gridDim.x - 1) {
            g_counter = 0;
            double l = atomicAdd(&g_loss_sum, 0.0);   // coherent read of final sum
            if (writeLoss)
                out[(size_t)Nrows * D] = (float)(2.0 * l / ((double)Nrows * (double)D));
        }
    }
}

extern "C" void kernel_launch(void* const* d_in, const int* in_sizes, int n_in,
                              void* d_out, int out_size) {
    const float* x = (const float*)d_in[0];
    const float* E = (const float*)d_in[1];
    float* out = (float*)d_out;
    const int N = in_sizes[0] / D;

    cudaFuncSetAttribute(vq_main_kernel, cudaFuncAttributeMaxDynamicSharedMemorySize, S_TOTAL);

    vq_prep_kernel<<<KC, D>>>(E);
    vq_main_kernel<<<N / BROWS, THREADS, S_TOTAL>>>(x, out, out_size > N * D ? 1 : 0, N);
}

// round 5
// speedup vs baseline: 4.0431x; 1.3053x over previous
#include <cuda_runtime.h>
#include <cuda_fp16.h>
#include <cstdint>

#define D        64
#define KC       512
#define BROWS    256
#define THREADS  256
#define DELTA    8.0e-3f
#define C_OFS    16.0f

// ---------------- device globals (scratch; allocs forbidden) ----------------
__device__ __align__(16) __half g_e16[KC * D];     // fp16 codebook [k][d]
__device__ __align__(16) float  g_eT[KC * D];      // fp32 codebook [k][d] (transposed)
__device__ float  g_enormC2[KC];                   // -(||e_k||^2 + C)/2
__device__ double g_loss_sum;
__device__ int    g_counter = 0;

// ---------------- smem layout (dynamic) ----------------
#define S_E      0                      // 512 * 128B (fp16, swizzled)      = 65536
#define S_X      65536                  // 256 * 128B (fp16, swizzled)      = 32768
#define S_EN     98304                  // 512 * 4B                         = 2048
#define S_KMIN   100352                 // 256 * 4B                         = 1024
#define S_TOTAL  101376

__device__ __forceinline__ uint32_t smem_u32(const void* p) {
    uint32_t a;
    asm("{ .reg .u64 t; cvta.to.shared.u64 t, %1; cvt.u32.u64 %0, t; }" : "=r"(a) : "l"(p));
    return a;
}

__device__ __forceinline__ void ldmatrix_x4(uint32_t* r, uint32_t addr) {
    asm volatile("ldmatrix.sync.aligned.m8n8.x4.shared.b16 {%0,%1,%2,%3}, [%4];"
                 : "=r"(r[0]), "=r"(r[1]), "=r"(r[2]), "=r"(r[3]) : "r"(addr));
}

__device__ __forceinline__ void mma16816(float& c0, float& c1, float& c2, float& c3,
                                         const uint32_t* a, uint32_t b0, uint32_t b1) {
    asm volatile("mma.sync.aligned.m16n8k16.row.col.f32.f16.f16.f32 "
                 "{%0,%1,%2,%3}, {%4,%5,%6,%7}, {%8,%9}, {%0,%1,%2,%3};"
                 : "+f"(c0), "+f"(c1), "+f"(c2), "+f"(c3)
                 : "r"(a[0]), "r"(a[1]), "r"(a[2]), "r"(a[3]), "r"(b0), "r"(b1));
}

// ================= prep: fp16 codebook, fp32 transposed codebook, norms =================
__global__ void vq_prep_kernel(const float* __restrict__ E) {
    __shared__ float sq[D];
    int k = blockIdx.x, d = threadIdx.x;
    float e = E[d * KC + k];
    g_e16[k * D + d] = __float2half_rn(e);
    g_eT[k * D + d]  = e;
    sq[d] = e * e;
    __syncthreads();
    if (d == 0) {
        float s = 0.f;
        #pragma unroll
        for (int i = 0; i < D; i++) s += sq[i];
        g_enormC2[k] = -0.5f * (s + C_OFS);
        if (k == 0) g_loss_sum = 0.0;
    }
}

// ================= main =================
__global__ __launch_bounds__(THREADS, 2)
void vq_main_kernel(const float* __restrict__ x,
                    float* __restrict__ out,
                    int writeLoss, int Nrows) {
    extern __shared__ __align__(16) char sm[];
    const uint32_t sb = smem_u32(sm);
    __shared__ float red[8];

    const int tid  = threadIdx.x;
    const int w    = tid >> 5, lane = tid & 31;
    const int m4   = lane & 3,  q8  = lane >> 2;
    const int rowBase = blockIdx.x * BROWS;

    // ---- stage E fp16 (swizzled rows of 128B) ----
    {
        const uint4* ge = (const uint4*)g_e16;
        #pragma unroll
        for (int i = 0; i < 16; i++) {
            int f = i * THREADS + tid;            // 16B chunk id
            int c = f >> 3, seg = f & 7;
            *(uint4*)(sm + S_E + c * 128 + ((seg * 16) ^ ((c & 7) << 4))) = ge[f];
        }
        float* en = (float*)(sm + S_EN);
        en[tid] = g_enormC2[tid];
        en[THREADS + tid] = g_enormC2[THREADS + tid];
    }
    // ---- stage X fp16 (swizzled rows of 128B) ----
    {
        const float4* xg = (const float4*)(x + (size_t)rowBase * D);
        #pragma unroll
        for (int i = 0; i < 16; i++) {
            int f = i * THREADS + tid;            // float4 id
            float4 v = xg[f];
            int row = f >> 4, seg = f & 15;
            uint32_t h0 = __half_as_ushort(__float2half_rn(v.x));
            uint32_t h1 = __half_as_ushort(__float2half_rn(v.y));
            uint32_t h2 = __half_as_ushort(__float2half_rn(v.z));
            uint32_t h3 = __half_as_ushort(__float2half_rn(v.w));
            uint2 u = make_uint2(h0 | (h1 << 16), h2 | (h3 << 16));
            *(uint2*)(sm + S_X + row * 128 + ((seg * 8) ^ ((row & 7) << 4))) = u;
        }
    }
    __syncthreads();

    // ---- preload A fragments: 2 m16 tiles x 4 k-steps ----
    uint32_t afr[2][4][4];
    const int tb0 = w * 32;
    #pragma unroll
    for (int t2 = 0; t2 < 2; t2++) {
        #pragma unroll
        for (int s = 0; s < 4; s++) {
            int row = tb0 + t2 * 16 + (lane & 15);
            uint32_t off = (uint32_t)(s * 32 + (lane >> 4) * 16) ^ (uint32_t)((row & 7) << 4);
            ldmatrix_x4(afr[t2][s], sb + S_X + row * 128 + off);
        }
    }

    // ---- sweep 512 codes; top-2 via raw-bit umin (a < 0 always, so
    //      min score = max a = min uint bits; ties -> lower col) ----
    uint32_t k1[4], k2[4];
    #pragma unroll
    for (int i = 0; i < 4; i++) { k1[i] = 0xFFFFFFFFu; k2[i] = 0xFFFFFFFFu; }

    #pragma unroll 2
    for (int n0 = 0; n0 < KC; n0 += 8) {
        const int c = n0 + q8;
        const char* erow = sm + S_E + c * 128;
        const uint32_t swz = (uint32_t)((c & 7) << 4);
        uint32_t b[4][2];
        #pragma unroll
        for (int s = 0; s < 4; s++) {
            uint32_t doff = (uint32_t)(s * 32 + m4 * 4);
            b[s][0] = *(const uint32_t*)(erow + (doff ^ swz));
            b[s][1] = *(const uint32_t*)(erow + ((doff + 16) ^ swz));
        }
        float2 en2 = *(const float2*)(sm + S_EN + (n0 + 2 * m4) * 4);
        const uint32_t col0 = (uint32_t)(n0 + 2 * m4), col1 = col0 + 1;

        #pragma unroll
        for (int t2 = 0; t2 < 2; t2++) {
            float a0 = en2.x, a1 = en2.y, a2 = en2.x, a3 = en2.y;
            #pragma unroll
            for (int s = 0; s < 4; s++) mma16816(a0, a1, a2, a3, afr[t2][s], b[s][0], b[s][1]);

            // rowA = tb0 + t2*16 + q8 (a0,a1) ; rowB = rowA+8 (a2,a3)
            uint32_t key, mx;
            int iA = t2 * 2, iB = iA + 1;
            key = (__float_as_uint(a0) & 0xFFFFFE00u) | col0;
            mx = umax(k1[iA], key); k1[iA] = umin(k1[iA], key); k2[iA] = umin(k2[iA], mx);
            key = (__float_as_uint(a1) & 0xFFFFFE00u) | col1;
            mx = umax(k1[iA], key); k1[iA] = umin(k1[iA], key); k2[iA] = umin(k2[iA], mx);
            key = (__float_as_uint(a2) & 0xFFFFFE00u) | col0;
            mx = umax(k1[iB], key); k1[iB] = umin(k1[iB], key); k2[iB] = umin(k2[iB], mx);
            key = (__float_as_uint(a3) & 0xFFFFFE00u) | col1;
            mx = umax(k1[iB], key); k1[iB] = umin(k1[iB], key); k2[iB] = umin(k2[iB], mx);
        }
    }

    // ---- merge top-2 across the 4 lanes sharing each row ----
    #pragma unroll
    for (int i = 0; i < 4; i++) {
        #pragma unroll
        for (int off = 1; off <= 2; off <<= 1) {
            uint32_t o1 = __shfl_xor_sync(0xffffffffu, k1[i], off);
            uint32_t o2 = __shfl_xor_sync(0xffffffffu, k2[i], off);
            uint32_t mx = umax(k1[i], o1);
            k1[i] = umin(k1[i], o1);
            k2[i] = umin(umin(k2[i], o2), mx);
        }
    }

    // ---- finalize rows: certified refinement on narrow gaps ----
    int* skm = (int*)(sm + S_KMIN);
    if (m4 == 0) {
        const float* en = (const float*)(sm + S_EN);
        #pragma unroll
        for (int i = 0; i < 4; i++) {
            int row = tb0 + (i >> 1) * 16 + q8 + (i & 1) * 8;
            int c1 = (int)(k1[i] & 511u), c2 = (int)(k2[i] & 511u);
            float f1 = __uint_as_float(k1[i] & 0xFFFFFE00u);   // a1' (best, largest a)
            float f2 = __uint_as_float(k2[i] & 0xFFFFFE00u);   // a2'
            int kmin = c1;
            if (2.f * (f1 - f2) < DELTA) {
                const float* xr = x + (size_t)(rowBase + row) * D;
                const float* e1 = g_eT + c1 * D;
                const float* e2 = g_eT + c2 * D;
                float p0 = 0.f, p1 = 0.f, p2 = 0.f, p3 = 0.f;
                float r0 = 0.f, r1 = 0.f, r2 = 0.f, r3 = 0.f;
                #pragma unroll
                for (int d = 0; d < D; d += 4) {
                    float x0 = xr[d], x1 = xr[d+1], x2 = xr[d+2], x3 = xr[d+3];
                    p0 = fmaf(x0, e1[d],   p0); p1 = fmaf(x1, e1[d+1], p1);
                    p2 = fmaf(x2, e1[d+2], p2); p3 = fmaf(x3, e1[d+3], p3);
                    r0 = fmaf(x0, e2[d],   r0); r1 = fmaf(x1, e2[d+1], r1);
                    r2 = fmaf(x2, e2[d+2], r2); r3 = fmaf(x3, e2[d+3], r3);
                }
                float s1 = -2.f * (((p0 + p1) + (p2 + p3)) + en[c1]);
                float s2 = -2.f * (((r0 + r1) + (r2 + r3)) + en[c2]);
                if (s2 < s1 || (s2 == s1 && c2 < c1)) kmin = c2;
            }
            skm[row] = kmin;
        }
    }
    __syncthreads();

    // ---- epilogue: coalesced straight-through output + loss (exact fp32 q) ----
    float lsum = 0.f;
    const float* xg = x   + (size_t)rowBase * D;
    float*       og = out + (size_t)rowBase * D;
    #pragma unroll 4
    for (int j = 0; j < (BROWS * D) / THREADS; j++) {
        int idx = j * THREADS + tid;
        int r = idx >> 6, d = idx & 63;
        float q  = g_eT[skm[r] * D + d];
        float xv = xg[idx];
        float t = q - xv;
        og[idx] = xv + t;
        lsum = fmaf(t, t, lsum);
    }
    #pragma unroll
    for (int o = 16; o > 0; o >>= 1) lsum += __shfl_xor_sync(0xffffffffu, lsum, o);
    if (lane == 0) red[w] = lsum;
    __syncthreads();
    if (tid == 0) {
        float s = 0.f;
        #pragma unroll
        for (int i = 0; i < 8; i++) s += red[i];
        atomicAdd(&g_loss_sum, (double)s);
        __threadfence();
        int old = atomicAdd(&g_counter, 1);
        if (old == (int)gridDim.x - 1) {
            g_counter = 0;
            double l = atomicAdd(&g_loss_sum, 0.0);   // coherent read of final sum
            if (writeLoss)
                out[(size_t)Nrows * D] = (float)(2.0 * l / ((double)Nrows * (double)D));
        }
    }
}

extern "C" void kernel_launch(void* const* d_in, const int* in_sizes, int n_in,
                              void* d_out, int out_size) {
    const float* x = (const float*)d_in[0];
    const float* E = (const float*)d_in[1];
    float* out = (float*)d_out;
    const int N = in_sizes[0] / D;

    cudaFuncSetAttribute(vq_main_kernel, cudaFuncAttributeMaxDynamicSharedMemorySize, S_TOTAL);

    vq_prep_kernel<<<KC, D>>>(E);
    vq_main_kernel<<<N / BROWS, THREADS, S_TOTAL>>>(x, out, out_size > N * D ? 1 : 0, N);
}